// round 9
// baseline (speedup 1.0000x reference)
#include <cuda_runtime.h>
#include <cuda_bf16.h>

// Problem constants
#define B_ 1024
#define T_ 256
#define V_ 50000
#define E_ 512
#define U_ 1024

// GEMM tiling
#define BM 128
#define BN 64
#define BK 16
#define ASTRIDE (BM + 4)   // 132: keeps 16B alignment for LDS.128, reduces STS conflicts
#define NBLK 128           // persistent grid: (1024/BM) * (1024/BN) = 8*16

// Scratch (device globals: allocation-free per harness rules)
__device__ float g_EW0[(size_t)V_ * U_];       // 204.8 MB: emb @ W0, gathered per step
__device__ float g_H0[2 * B_ * U_];            // ping-pong hidden state layer 0
__device__ float g_H1[2 * B_ * U_];            // ping-pong hidden state layer 1
__device__ unsigned g_bar_count = 0;
__device__ volatile unsigned g_bar_gen = 0;

// ---------------------------------------------------------------------------
// Grid-wide barrier (128 resident CTAs). Release via gen counter; count reset
// by releaser. threadfence publishes H writes (stores are .cg -> L2 anyway).
// ---------------------------------------------------------------------------
__device__ __forceinline__ void grid_sync() {
    __syncthreads();
    if (threadIdx.x == 0) {
        __threadfence();
        unsigned g = g_bar_gen;
        unsigned a = atomicAdd(&g_bar_count, 1);
        if (a == NBLK - 1) {
            g_bar_count = 0;
            __threadfence();
            g_bar_gen = g + 1;
        } else {
            while (g_bar_gen == g) { __nanosleep(32); }
        }
        __threadfence();
    }
    __syncthreads();
}

// ---------------------------------------------------------------------------
// Shared SGEMM mainloop: C_tile(128x64) += A[rows,K] * B[K,cols]
// 256 threads, 8x4 per thread, double-buffered smem.
// ACG=true -> A loaded with .cg (mutable H state; L1 is stale across SMs).
// ---------------------------------------------------------------------------
__device__ __forceinline__ float4 ld4_cg(const float* p) { return __ldcg((const float4*)p); }
__device__ __forceinline__ float4 ld4_ro(const float* p) { return __ldg((const float4*)p); }

template <bool ACG>
__device__ __forceinline__ void gt_loadA(float4 aR[2], const float* A, int lda,
                                         int rowBase, int kBase, int maxRow, int tid) {
#pragma unroll
    for (int j = 0; j < 2; j++) {
        int i = tid + (j << 8);
        int arow = i >> 2;
        int acol = (i & 3) << 2;
        int r = rowBase + arow;
        if (r > maxRow) r = maxRow;
        const float* p = A + (size_t)r * lda + kBase + acol;
        aR[j] = ACG ? ld4_cg(p) : ld4_ro(p);
    }
}

__device__ __forceinline__ void gt_storeA(const float4 aR[2], float* AsBuf, int tid) {
#pragma unroll
    for (int j = 0; j < 2; j++) {
        int i = tid + (j << 8);
        int arow = i >> 2;
        int acol = (i & 3) << 2;
        AsBuf[(acol + 0) * ASTRIDE + arow] = aR[j].x;
        AsBuf[(acol + 1) * ASTRIDE + arow] = aR[j].y;
        AsBuf[(acol + 2) * ASTRIDE + arow] = aR[j].z;
        AsBuf[(acol + 3) * ASTRIDE + arow] = aR[j].w;
    }
}

__device__ __forceinline__ void gt_loadB(float4& bR, const float* Bm, int ldb,
                                         int colBase, int kBase, int tid) {
    int brow = tid >> 4;
    int bcol = (tid & 15) << 2;
    bR = ld4_ro(Bm + (size_t)(kBase + brow) * ldb + colBase + bcol);
}

__device__ __forceinline__ void gt_storeB(const float4 bR, float* BsBuf, int tid) {
    int brow = tid >> 4;
    int bcol = (tid & 15) << 2;
    *(float4*)(BsBuf + brow * BN + bcol) = bR;
}

template <bool ACG>
__device__ __forceinline__ void gemm_tile(const float* __restrict__ A, int lda, int maxRow,
                                          const float* __restrict__ Bm, int ldb, int K,
                                          int rowBase, int colBase,
                                          float* AsS, float* BsS,
                                          float acc[8][4], int tid) {
    const int ABUF = BK * ASTRIDE;
    const int BBUF = BK * BN;
    const int tx = tid & 15;
    const int ty = tid >> 4;

    float4 aR[2];
    float4 bR;
    gt_loadA<ACG>(aR, A, lda, rowBase, 0, maxRow, tid);
    gt_loadB(bR, Bm, ldb, colBase, 0, tid);
    gt_storeA(aR, AsS, tid);
    gt_storeB(bR, BsS, tid);
    __syncthreads();

    const int nC = K >> 4;
#pragma unroll 2
    for (int c = 0; c < nC; c++) {
        const int cur = c & 1;
        if (c + 1 < nC) {
            gt_loadA<ACG>(aR, A, lda, rowBase, (c + 1) << 4, maxRow, tid);
            gt_loadB(bR, Bm, ldb, colBase, (c + 1) << 4, tid);
        }
        const float* As = AsS + cur * ABUF;
        const float* Bs = BsS + cur * BBUF;
#pragma unroll 8
        for (int k = 0; k < BK; k++) {
            float4 a0 = *(const float4*)(As + k * ASTRIDE + (ty << 3));
            float4 a1 = *(const float4*)(As + k * ASTRIDE + (ty << 3) + 4);
            float4 bv = *(const float4*)(Bs + k * BN + (tx << 2));
            float av[8] = {a0.x, a0.y, a0.z, a0.w, a1.x, a1.y, a1.z, a1.w};
            float bw[4] = {bv.x, bv.y, bv.z, bv.w};
#pragma unroll
            for (int i = 0; i < 8; i++)
#pragma unroll
                for (int j = 0; j < 4; j++)
                    acc[i][j] = fmaf(av[i], bw[j], acc[i][j]);
        }
        if (c + 1 < nC) {
            gt_storeA(aR, AsS + (cur ^ 1) * ABUF, tid);
            gt_storeB(bR, BsS + (cur ^ 1) * BBUF, tid);
        }
        __syncthreads();
    }
}

// ---------------------------------------------------------------------------
// Phase 1: EW0[V,U] = emb[V,E] @ W0[E,U]   (52 GF, embarrassingly parallel)
// ---------------------------------------------------------------------------
__global__ void __launch_bounds__(256) k_ew0(const float* __restrict__ emb,
                                             const float* __restrict__ W0) {
    __shared__ float AsS[2 * BK * ASTRIDE];
    __shared__ float BsS[2 * BK * BN];
    const int tid = threadIdx.x;
    const int tx = tid & 15;
    const int ty = tid >> 4;
    const int rowBase = blockIdx.x << 7;
    const int colBase = blockIdx.y << 6;

    float acc[8][4];
#pragma unroll
    for (int i = 0; i < 8; i++)
#pragma unroll
        for (int j = 0; j < 4; j++) acc[i][j] = 0.f;

    gemm_tile<false>(emb, E_, V_ - 1, W0, U_, E_, rowBase, colBase, AsS, BsS, acc, tid);

#pragma unroll
    for (int i = 0; i < 8; i++) {
        int r = rowBase + (ty << 3) + i;
        if (r < V_) {
            float4 o = make_float4(acc[i][0], acc[i][1], acc[i][2], acc[i][3]);
            *(float4*)(g_EW0 + (size_t)r * U_ + colBase + (tx << 2)) = o;
        }
    }
}

// ---------------------------------------------------------------------------
// Phase 2: persistent RNN. 128 CTAs; each owns one 128x64 tile of H.
// Per step:  H0c = tanh(EW0[idx] + H0p@U0 + b0)   -> sync
//            H1c = tanh(H0c@W1 + H1p@U1 + b1)     -> sync
// ---------------------------------------------------------------------------
__global__ void __launch_bounds__(256, 1) k_rnn_persistent(
    const int* __restrict__ inputs,
    const float* __restrict__ U0, const float* __restrict__ b0,
    const float* __restrict__ W1, const float* __restrict__ U1,
    const float* __restrict__ b1) {
    __shared__ float AsS[2 * BK * ASTRIDE];
    __shared__ float BsS[2 * BK * BN];
    const int tid = threadIdx.x;
    const int bid = blockIdx.x;
    const int tx = tid & 15;
    const int ty = tid >> 4;
    const int rowBase = (bid >> 4) << 7;  // 8 row tiles of 128
    const int colBase = (bid & 15) << 6;  // 16 col tiles of 64

    // Zero-init parity-0 state buffers (read at t=0). .cg stores -> L2 visible.
    {
        float4 z = make_float4(0.f, 0.f, 0.f, 0.f);
        float4* h0 = (float4*)g_H0;
        float4* h1 = (float4*)g_H1;
        for (int i = (bid << 8) + tid; i < (B_ * U_ / 4); i += NBLK * 256) {
            __stcg(h0 + i, z);
            __stcg(h1 + i, z);
        }
    }
    grid_sync();

    const float4 b0v = *(const float4*)(b0 + colBase + (tx << 2));
    const float4 b1v = *(const float4*)(b1 + colBase + (tx << 2));

#pragma unroll 1
    for (int t = 0; t < T_; t++) {
        const int pv = t & 1;
        const int cu = pv ^ 1;
        const float* H0p = g_H0 + (size_t)pv * (B_ * U_);
        float* H0c = g_H0 + (size_t)cu * (B_ * U_);
        const float* H1p = g_H1 + (size_t)pv * (B_ * U_);
        float* H1c = g_H1 + (size_t)cu * (B_ * U_);

        // --- layer 0: acc = EW0[inputs[b,t]] + b0; acc += H0p @ U0 ---
        float acc[8][4];
#pragma unroll
        for (int i = 0; i < 8; i++) {
            int r = rowBase + (ty << 3) + i;
            int idx = __ldg(inputs + r * T_ + t);
            float4 p = ld4_ro(g_EW0 + (size_t)idx * U_ + colBase + (tx << 2));
            acc[i][0] = p.x + b0v.x;
            acc[i][1] = p.y + b0v.y;
            acc[i][2] = p.z + b0v.z;
            acc[i][3] = p.w + b0v.w;
        }
        gemm_tile<true>(H0p, U_, B_ - 1, U0, U_, U_, rowBase, colBase, AsS, BsS, acc, tid);
#pragma unroll
        for (int i = 0; i < 8; i++) {
            int r = rowBase + (ty << 3) + i;
            float4 o = make_float4(tanhf(acc[i][0]), tanhf(acc[i][1]),
                                   tanhf(acc[i][2]), tanhf(acc[i][3]));
            __stcg((float4*)(H0c + (size_t)r * U_ + colBase + (tx << 2)), o);
        }
        grid_sync();

        // --- layer 1: acc = b1; acc += H0c @ W1; acc += H1p @ U1 ---
#pragma unroll
        for (int i = 0; i < 8; i++) {
            acc[i][0] = b1v.x;
            acc[i][1] = b1v.y;
            acc[i][2] = b1v.z;
            acc[i][3] = b1v.w;
        }
        gemm_tile<true>(H0c, U_, B_ - 1, W1, U_, U_, rowBase, colBase, AsS, BsS, acc, tid);
        gemm_tile<true>(H1p, U_, B_ - 1, U1, U_, U_, rowBase, colBase, AsS, BsS, acc, tid);
#pragma unroll
        for (int i = 0; i < 8; i++) {
            int r = rowBase + (ty << 3) + i;
            float4 o = make_float4(tanhf(acc[i][0]), tanhf(acc[i][1]),
                                   tanhf(acc[i][2]), tanhf(acc[i][3]));
            __stcg((float4*)(H1c + (size_t)r * U_ + colBase + (tx << 2)), o);
        }
        grid_sync();
    }
}

// ---------------------------------------------------------------------------
// Phase 3: out[b] = sigmoid(H1_final[b,:] . Wout + bout)
// Final state is parity 0 (T=256 even). One CTA per batch row.
// ---------------------------------------------------------------------------
__global__ void __launch_bounds__(128) k_out(const float* __restrict__ Wout,
                                             const float* __restrict__ bout,
                                             float* __restrict__ out) {
    const int b = blockIdx.x;
    const int tid = threadIdx.x;
    __shared__ float red[128];
    const float* h = g_H1 + (size_t)b * U_;  // parity-0 buffer
    float s = 0.f;
    for (int u = tid; u < U_; u += 128) s += h[u] * Wout[u];
    red[tid] = s;
    __syncthreads();
    for (int o = 64; o > 0; o >>= 1) {
        if (tid < o) red[tid] += red[tid + o];
        __syncthreads();
    }
    if (tid == 0) {
        float z = red[0] + bout[0];
        out[b] = 1.f / (1.f + expf(-z));
    }
}

// ---------------------------------------------------------------------------
extern "C" void kernel_launch(void* const* d_in, const int* in_sizes, int n_in,
                              void* d_out, int out_size) {
    const int* inputs = (const int*)d_in[0];
    const float* emb = (const float*)d_in[1];
    const float* W0 = (const float*)d_in[2];
    const float* U0 = (const float*)d_in[3];
    const float* b0 = (const float*)d_in[4];
    const float* W1 = (const float*)d_in[5];
    const float* U1 = (const float*)d_in[6];
    const float* b1 = (const float*)d_in[7];
    const float* Wout = (const float*)d_in[8];
    const float* bout = (const float*)d_in[9];
    float* out = (float*)d_out;

    dim3 g1((V_ + BM - 1) / BM, U_ / BN);  // 391 x 16
    k_ew0<<<g1, 256>>>(emb, W0);
    k_rnn_persistent<<<NBLK, 256>>>(inputs, U0, b0, W1, U1, b1);
    k_out<<<B_, 128>>>(Wout, bout, out);
}

// round 11
// speedup vs baseline: 3.7838x; 3.7838x over previous
#include <cuda_runtime.h>
#include <cuda_bf16.h>
#include <cstdint>

// ---------------------------------------------------------------------------
// Feature gate: tcgen05 only exists in arch-accelerated device passes.
// Non-accelerated passes (compute_103 -> sm_103) compile the fp32 fallback.
// ---------------------------------------------------------------------------
#if defined(__CUDA_ARCH_FEAT_SM103_ALL) || defined(__CUDA_ARCH_FEAT_SM100_ALL) || \
    defined(__CUDA_ARCH_FEAT_SM101_ALL) || defined(__CUDA_ARCH_FEAT_SM110_ALL)
#define HAS_TC 1
#else
#define HAS_TC 0
#endif

// Problem constants
#define B_ 1024
#define T_ 256
#define V_ 50000
#define E_ 512
#define U_ 1024

// fp32 SGEMM tiling (k_ew0 + fallback)
#define BM 128
#define BN 64
#define BK 16
#define ASTRIDE (BM + 4)
#define NBLK 128

// tcgen05 recurrence
#define TM 128
#define TN 64
#define HTILE 16384                 // 128 rows x 128B (64 bf16), SW128-swizzled
#define WTILE 8192                  // 64 rows x 128B
#define HPAR  (128 * HTILE)         // one parity: 8 rb x 16 chunks
#define HBYTES (2 * HPAR)
#define WBYTES (256 * WTILE)

#define TMEM_PTR 64
#define SLOT0 1024
#define SLOTSZ 49152
#define A_HI 0
#define A_LO 16384
#define B_HI 32768
#define B_LO 40960
#define DSMEM (1024 + SLOT0 + 2 * SLOTSZ)   // align pad + header + 2 slots

#define IDESC ((1u << 4) | (1u << 7) | (1u << 10) | ((TN / 8) << 17) | ((TM / 16) << 24))

// Device scratch (allocation-free per harness rules)
__device__ float g_EW0[(size_t)V_ * U_];
// fp32 fallback state
__device__ float g_H0f[2 * B_ * U_];
__device__ float g_H1f[2 * B_ * U_];
// tile-format split-bf16 state
__device__ __align__(1024) char g_H0_hi[HBYTES];
__device__ __align__(1024) char g_H0_lo[HBYTES];
__device__ __align__(1024) char g_H1_hi[HBYTES];
__device__ __align__(1024) char g_H1_lo[HBYTES];
__device__ __align__(1024) char g_U0t_hi[WBYTES];
__device__ __align__(1024) char g_U0t_lo[WBYTES];
__device__ __align__(1024) char g_W1t_hi[WBYTES];
__device__ __align__(1024) char g_W1t_lo[WBYTES];
__device__ __align__(1024) char g_U1t_hi[WBYTES];
__device__ __align__(1024) char g_U1t_lo[WBYTES];
__device__ unsigned g_bar_count = 0;
__device__ volatile unsigned g_bar_gen = 0;

// ---------------------------------------------------------------------------
// Common helpers
// ---------------------------------------------------------------------------
__device__ __forceinline__ float4 ld4_ro(const float* p) { return __ldg((const float4*)p); }
__device__ __forceinline__ float4 ld4_cg(const float* p) { return __ldcg((const float4*)p); }

__device__ __forceinline__ void grid_sync() {
    __syncthreads();
#if HAS_TC
    asm volatile("fence.proxy.async;" ::: "memory");
#endif
    if (threadIdx.x == 0) {
        __threadfence();
        unsigned g = g_bar_gen;
        unsigned a = atomicAdd(&g_bar_count, 1);
        if (a == NBLK - 1) {
            g_bar_count = 0;
            __threadfence();
            g_bar_gen = g + 1;
        } else {
            while (g_bar_gen == g) { __nanosleep(32); }
        }
        __threadfence();
    }
    __syncthreads();
}

#if HAS_TC
// ---------------------------------------------------------------------------
// tcgen05 / TMA / mbarrier PTX helpers (accelerated pass only)
// ---------------------------------------------------------------------------
__device__ __forceinline__ uint32_t smem_u32(const void* p) {
    return (uint32_t)__cvta_generic_to_shared(p);
}
__device__ __forceinline__ void mbar_init(uint32_t a, uint32_t cnt) {
    asm volatile("mbarrier.init.shared.b64 [%0], %1;" :: "r"(a), "r"(cnt) : "memory");
}
__device__ __forceinline__ void mbar_expect(uint32_t a, uint32_t bytes) {
    asm volatile("mbarrier.arrive.expect_tx.shared.b64 _, [%0], %1;"
                 :: "r"(a), "r"(bytes) : "memory");
}
__device__ __forceinline__ void mbar_wait(uint32_t a, uint32_t parity) {
    asm volatile(
        "{\n\t.reg .pred P;\n\t"
        "WL%=:\n\t"
        "mbarrier.try_wait.parity.acquire.cta.shared::cta.b64 P, [%0], %1, 0x989680;\n\t"
        "@P bra WD%=;\n\t"
        "bra WL%=;\n\t"
        "WD%=:\n\t}"
        :: "r"(a), "r"(parity) : "memory");
}
__device__ __forceinline__ void bulk_g2s(uint32_t dst, const void* src,
                                         uint32_t bytes, uint32_t mbar) {
    asm volatile(
        "cp.async.bulk.shared::cta.global.mbarrier::complete_tx::bytes [%0], [%1], %2, [%3];"
        :: "r"(dst), "l"(src), "r"(bytes), "r"(mbar) : "memory");
}
__device__ __forceinline__ uint64_t sdesc(uint32_t addr) {
    // SW128 K-major: layout=2, version=1, SBO=64, LBO=1
    return 0x4000404000010000ULL | ((uint64_t)(addr >> 4) & 0x3FFF);
}
__device__ __forceinline__ void mma_f16_ss(uint32_t d, uint64_t ad, uint64_t bd,
                                           uint32_t idesc, uint32_t en) {
    asm volatile(
        "{\n\t.reg .pred p;\n\t"
        "setp.ne.u32 p, %4, 0;\n\t"
        "tcgen05.mma.cta_group::1.kind::f16 [%0], %1, %2, %3, {%5, %5, %5, %5}, p;\n\t}"
        :: "r"(d), "l"(ad), "l"(bd), "r"(idesc), "r"(en), "r"(0u) : "memory");
}
__device__ __forceinline__ void mma_commit(uint32_t mbar) {
    asm volatile(
        "tcgen05.commit.cta_group::1.mbarrier::arrive::one.shared::cluster.b64 [%0];"
        :: "r"(mbar) : "memory");
}
#define TC_FENCE_AFTER()  asm volatile("tcgen05.fence::after_thread_sync;" ::: "memory")
#define TC_FENCE_BEFORE() asm volatile("tcgen05.fence::before_thread_sync;" ::: "memory")
#define TC_WAIT_LD()      asm volatile("tcgen05.wait::ld.sync.aligned;" ::: "memory")

#define LDTM_X32(r, ta) \
    asm volatile( \
        "tcgen05.ld.sync.aligned.32x32b.x32.b32 " \
        "{%0, %1, %2, %3, %4, %5, %6, %7, " \
        " %8, %9, %10, %11, %12, %13, %14, %15, " \
        " %16, %17, %18, %19, %20, %21, %22, %23, " \
        " %24, %25, %26, %27, %28, %29, %30, %31}, [%32];" \
        : "=r"((r)[0]),  "=r"((r)[1]),  "=r"((r)[2]),  "=r"((r)[3]), \
          "=r"((r)[4]),  "=r"((r)[5]),  "=r"((r)[6]),  "=r"((r)[7]), \
          "=r"((r)[8]),  "=r"((r)[9]),  "=r"((r)[10]), "=r"((r)[11]), \
          "=r"((r)[12]), "=r"((r)[13]), "=r"((r)[14]), "=r"((r)[15]), \
          "=r"((r)[16]), "=r"((r)[17]), "=r"((r)[18]), "=r"((r)[19]), \
          "=r"((r)[20]), "=r"((r)[21]), "=r"((r)[22]), "=r"((r)[23]), \
          "=r"((r)[24]), "=r"((r)[25]), "=r"((r)[26]), "=r"((r)[27]), \
          "=r"((r)[28]), "=r"((r)[29]), "=r"((r)[30]), "=r"((r)[31]) \
        : "r"(ta))

struct Seg { const char *ah, *al, *bh, *bl; };

// Pipelined bulk-copy + MMA issue for one layer (nseg segments of 16 K-chunks)
__device__ __forceinline__ void ctrl_run(uint32_t sbase, uint32_t tmem,
                                         Seg s0, Seg s1, int nseg,
                                         int* nf, int* nc) {
    const int nT = nseg << 4;
    auto fill = [&](int gc) {
        int s = gc & 1;
        if (nf[s] > 0) mbar_wait(sbase + 16 + s * 8, (nf[s] - 1) & 1);
        uint32_t fb = sbase + s * 8;
        uint32_t dst = sbase + SLOT0 + s * SLOTSZ;
        const Seg& sg = (gc >> 4) ? s1 : s0;
        int c = gc & 15;
        mbar_expect(fb, SLOTSZ);
        bulk_g2s(dst + A_HI, sg.ah + (size_t)c * HTILE, HTILE, fb);
        bulk_g2s(dst + A_LO, sg.al + (size_t)c * HTILE, HTILE, fb);
        bulk_g2s(dst + B_HI, sg.bh + (size_t)c * WTILE, WTILE, fb);
        bulk_g2s(dst + B_LO, sg.bl + (size_t)c * WTILE, WTILE, fb);
        nf[s]++;
    };
    fill(0);
    fill(1);
    for (int gc = 0; gc < nT; gc++) {
        int s = gc & 1;
        mbar_wait(sbase + s * 8, nc[s] & 1);
        uint32_t sa = sbase + SLOT0 + s * SLOTSZ;
        uint64_t dAh = sdesc(sa + A_HI), dAl = sdesc(sa + A_LO);
        uint64_t dBh = sdesc(sa + B_HI), dBl = sdesc(sa + B_LO);
        uint32_t en = (gc > 0) ? 1u : 0u;
#pragma unroll
        for (int k = 0; k < 4; k++) { mma_f16_ss(tmem, dAh + k * 2, dBh + k * 2, IDESC, en); en = 1u; }
#pragma unroll
        for (int k = 0; k < 4; k++) mma_f16_ss(tmem, dAl + k * 2, dBh + k * 2, IDESC, 1u);
#pragma unroll
        for (int k = 0; k < 4; k++) mma_f16_ss(tmem, dAh + k * 2, dBl + k * 2, IDESC, 1u);
        mma_commit(sbase + 16 + s * 8);
        nc[s]++;
        if (gc == nT - 1) mma_commit(sbase + 32);
        if (gc + 2 < nT) fill(gc + 2);
    }
}
#endif  // HAS_TC

// ---------------------------------------------------------------------------
// fp32 SGEMM building blocks (k_ew0 always; k_rnn fallback)
// ---------------------------------------------------------------------------
template <bool ACG>
__device__ __forceinline__ void gt_loadA(float4 aR[2], const float* A, int lda,
                                         int rowBase, int kBase, int maxRow, int tid) {
#pragma unroll
    for (int j = 0; j < 2; j++) {
        int i = tid + (j << 8);
        int arow = i >> 2;
        int acol = (i & 3) << 2;
        int r = rowBase + arow;
        if (r > maxRow) r = maxRow;
        const float* p = A + (size_t)r * lda + kBase + acol;
        aR[j] = ACG ? ld4_cg(p) : ld4_ro(p);
    }
}
__device__ __forceinline__ void gt_storeA(const float4 aR[2], float* AsBuf, int tid) {
#pragma unroll
    for (int j = 0; j < 2; j++) {
        int i = tid + (j << 8);
        int arow = i >> 2;
        int acol = (i & 3) << 2;
        AsBuf[(acol + 0) * ASTRIDE + arow] = aR[j].x;
        AsBuf[(acol + 1) * ASTRIDE + arow] = aR[j].y;
        AsBuf[(acol + 2) * ASTRIDE + arow] = aR[j].z;
        AsBuf[(acol + 3) * ASTRIDE + arow] = aR[j].w;
    }
}
__device__ __forceinline__ void gt_loadB(float4& bR, const float* Bm, int ldb,
                                         int colBase, int kBase, int tid) {
    int brow = tid >> 4;
    int bcol = (tid & 15) << 2;
    bR = ld4_ro(Bm + (size_t)(kBase + brow) * ldb + colBase + bcol);
}
__device__ __forceinline__ void gt_storeB(const float4 bR, float* BsBuf, int tid) {
    int brow = tid >> 4;
    int bcol = (tid & 15) << 2;
    *(float4*)(BsBuf + brow * BN + bcol) = bR;
}

template <bool ACG>
__device__ __forceinline__ void gemm_tile(const float* __restrict__ A, int lda, int maxRow,
                                          const float* __restrict__ Bm, int ldb, int K,
                                          int rowBase, int colBase,
                                          float* AsS, float* BsS,
                                          float acc[8][4], int tid) {
    const int ABUF = BK * ASTRIDE;
    const int BBUF = BK * BN;
    const int tx = tid & 15;
    const int ty = tid >> 4;
    float4 aR[2];
    float4 bR;
    gt_loadA<ACG>(aR, A, lda, rowBase, 0, maxRow, tid);
    gt_loadB(bR, Bm, ldb, colBase, 0, tid);
    gt_storeA(aR, AsS, tid);
    gt_storeB(bR, BsS, tid);
    __syncthreads();
    const int nC = K >> 4;
#pragma unroll 2
    for (int c = 0; c < nC; c++) {
        const int cur = c & 1;
        if (c + 1 < nC) {
            gt_loadA<ACG>(aR, A, lda, rowBase, (c + 1) << 4, maxRow, tid);
            gt_loadB(bR, Bm, ldb, colBase, (c + 1) << 4, tid);
        }
        const float* As = AsS + cur * ABUF;
        const float* Bs = BsS + cur * BBUF;
#pragma unroll 8
        for (int k = 0; k < BK; k++) {
            float4 a0 = *(const float4*)(As + k * ASTRIDE + (ty << 3));
            float4 a1 = *(const float4*)(As + k * ASTRIDE + (ty << 3) + 4);
            float4 bv = *(const float4*)(Bs + k * BN + (tx << 2));
            float av[8] = {a0.x, a0.y, a0.z, a0.w, a1.x, a1.y, a1.z, a1.w};
            float bw[4] = {bv.x, bv.y, bv.z, bv.w};
#pragma unroll
            for (int i = 0; i < 8; i++)
#pragma unroll
                for (int j = 0; j < 4; j++)
                    acc[i][j] = fmaf(av[i], bw[j], acc[i][j]);
        }
        if (c + 1 < nC) {
            gt_storeA(aR, AsS + (cur ^ 1) * ABUF, tid);
            gt_storeB(bR, BsS + (cur ^ 1) * BBUF, tid);
        }
        __syncthreads();
    }
}

// ---------------------------------------------------------------------------
// k_ew0: EW0[V,U] = emb[V,E] @ W0[E,U]  (fp32, both paths)
// ---------------------------------------------------------------------------
__global__ void __launch_bounds__(256) k_ew0(const float* __restrict__ emb,
                                             const float* __restrict__ W0) {
    __shared__ float AsS[2 * BK * ASTRIDE];
    __shared__ float BsS[2 * BK * BN];
    const int tid = threadIdx.x;
    const int tx = tid & 15;
    const int ty = tid >> 4;
    const int rowBase = blockIdx.x << 7;
    const int colBase = blockIdx.y << 6;
    float acc[8][4];
#pragma unroll
    for (int i = 0; i < 8; i++)
#pragma unroll
        for (int j = 0; j < 4; j++) acc[i][j] = 0.f;
    gemm_tile<false>(emb, E_, V_ - 1, W0, U_, E_, rowBase, colBase, AsS, BsS, acc, tid);
#pragma unroll
    for (int i = 0; i < 8; i++) {
        int r = rowBase + (ty << 3) + i;
        if (r < V_) {
            float4 o = make_float4(acc[i][0], acc[i][1], acc[i][2], acc[i][3]);
            *(float4*)(g_EW0 + (size_t)r * U_ + colBase + (tx << 2)) = o;
        }
    }
}

// ---------------------------------------------------------------------------
// k_prep: transposed split-bf16 weight tiles (SW128, K-major). Cheap; both paths.
// ---------------------------------------------------------------------------
__global__ void __launch_bounds__(256) k_prep(const float* __restrict__ U0,
                                              const float* __restrict__ W1,
                                              const float* __restrict__ U1) {
    const float* W = (blockIdx.y == 0) ? U0 : (blockIdx.y == 1 ? W1 : U1);
    char* dh = (blockIdx.y == 0) ? g_U0t_hi : (blockIdx.y == 1 ? g_W1t_hi : g_U1t_hi);
    char* dl = (blockIdx.y == 0) ? g_U0t_lo : (blockIdx.y == 1 ? g_W1t_lo : g_U1t_lo);
    const int nb = blockIdx.x >> 4;
    const int c = blockIdx.x & 15;
    char* th = dh + (size_t)blockIdx.x * WTILE;
    char* tl = dl + (size_t)blockIdx.x * WTILE;
    const int tid = threadIdx.x;
    for (int i = tid; i < 512; i += 256) {
        int nl = i >> 3;
        int kg = i & 7;
        int n = (nb << 6) + nl;
        int kbase = (c << 6) + (kg << 3);
        union { __nv_bfloat16 b[8]; uint4 v; } ph, pl;
#pragma unroll
        for (int j = 0; j < 8; j++) {
            float v = __ldg(W + (size_t)(kbase + j) * U_ + n);
            __nv_bfloat16 hb = __float2bfloat16(v);
            ph.b[j] = hb;
            pl.b[j] = __float2bfloat16(v - __bfloat162float(hb));
        }
        uint32_t off = (nl << 7) + (kg << 4);
        uint32_t sw = off ^ ((off >> 3) & 0x70);
        *(uint4*)(th + sw) = ph.v;
        *(uint4*)(tl + sw) = pl.v;
    }
}

// Zero parity-0 state (both representations; must re-zero every launch)
__global__ void __launch_bounds__(256) k_zero() {
    size_t i = (size_t)blockIdx.x * blockDim.x + threadIdx.x;  // 16B units
    uint4 z = make_uint4(0, 0, 0, 0);
    if (i < (size_t)B_ * U_ / 4) {          // fp32 parity-0: 4MB each
        ((uint4*)g_H0f)[i] = z;
        ((uint4*)g_H1f)[i] = z;
    }
    if (i < HPAR / 16) {                    // tile parity-0: 2MB each
        ((uint4*)g_H0_hi)[i] = z;
        ((uint4*)g_H0_lo)[i] = z;
        ((uint4*)g_H1_hi)[i] = z;
        ((uint4*)g_H1_lo)[i] = z;
    }
}

// ---------------------------------------------------------------------------
// k_rnn: persistent recurrence. 128 CTAs x 256 threads.
//   HAS_TC : split-bf16 tcgen05 pipeline (TMEM accum, cp.async.bulk slots)
//   else   : proven fp32 FFMA SGEMM path
// ---------------------------------------------------------------------------
__global__ void __launch_bounds__(256, 1) k_rnn(
    const int* __restrict__ inputs,
    const float* __restrict__ U0, const float* __restrict__ b0,
    const float* __restrict__ W1, const float* __restrict__ U1,
    const float* __restrict__ b1) {
    extern __shared__ __align__(16) char smem_raw[];
    const int tid = threadIdx.x;
    const int bid = blockIdx.x;

#if HAS_TC
    // ---------------- tcgen05 path ----------------
    const int wid = tid >> 5;
    const int lane = tid & 31;
    const int rb = bid >> 4;
    const int nb = bid & 15;
    const int rowBase = rb << 7;
    const int colBase = nb << 6;
    const int r = ((wid & 3) << 5) + lane;   // M row in tile (0..127)
    const int coff = (wid >> 2) << 5;        // column half: 0 or 32
    const size_t rb16 = (size_t)rb * 16 * HTILE;
    const size_t nb16 = (size_t)nb * 16 * WTILE;
    const size_t otile = ((size_t)rb * 16 + nb) * HTILE;

    uint32_t raw = smem_u32(smem_raw);
    uint32_t sbase = (raw + 1023) & ~1023u;
    char* sgen = smem_raw + (sbase - raw);
    float* sb0 = (float*)(sgen + 128);
    float* sb1 = (float*)(sgen + 384);

    if (tid == 0) {
        mbar_init(sbase + 0, 1);    // full slot 0
        mbar_init(sbase + 8, 1);    // full slot 1
        mbar_init(sbase + 16, 1);   // mma-done slot 0
        mbar_init(sbase + 24, 1);   // mma-done slot 1
        mbar_init(sbase + 32, 1);   // layer epilogue
    }
    if (tid < 64) {
        sb0[tid] = b0[colBase + tid];
        sb1[tid] = b1[colBase + tid];
    }
    if (wid == 0) {
        asm volatile("tcgen05.alloc.cta_group::1.sync.aligned.shared::cta.b32 [%0], %1;"
                     :: "r"(sbase + TMEM_PTR), "r"(64u) : "memory");
    }
    __syncthreads();
    uint32_t tmem;
    asm volatile("ld.shared.b32 %0, [%1];" : "=r"(tmem) : "r"(sbase + TMEM_PTR));

    grid_sync();   // k_zero visibility + CTA alignment

    int epi_ph = 0;
    int nf[2] = {0, 0}, nc[2] = {0, 0};

#pragma unroll 1
    for (int t = 0; t < T_; t++) {
        const int pv = t & 1;
        const int cu = pv ^ 1;

        // ===== layer 0: D = H0p @ U0t^T  (+ gather EW0 + b0 in epilogue) =====
        if (tid == 0) {
            Seg s0 = { g_H0_hi + (size_t)pv * HPAR + rb16,
                       g_H0_lo + (size_t)pv * HPAR + rb16,
                       g_U0t_hi + nb16, g_U0t_lo + nb16 };
            ctrl_run(sbase, tmem, s0, s0, 1, nf, nc);
        }
        const int idx = __ldg(inputs + (rowBase + r) * T_ + t);
        float gv[32];
#pragma unroll
        for (int i = 0; i < 8; i++) {
            float4 g4 = ld4_ro(g_EW0 + (size_t)idx * U_ + colBase + coff + i * 4);
            gv[i * 4 + 0] = g4.x; gv[i * 4 + 1] = g4.y;
            gv[i * 4 + 2] = g4.z; gv[i * 4 + 3] = g4.w;
        }
        mbar_wait(sbase + 32, epi_ph & 1);
        epi_ph++;
        TC_FENCE_AFTER();
        {
            uint32_t d[32];
            LDTM_X32(d, tmem + coff);
            TC_WAIT_LD();
            TC_FENCE_BEFORE();
            char* oh = g_H0_hi + (size_t)cu * HPAR + otile;
            char* ol = g_H0_lo + (size_t)cu * HPAR + otile;
#pragma unroll
            for (int i = 0; i < 4; i++) {
                union { __nv_bfloat16 b[8]; uint4 v; } ph, pl;
#pragma unroll
                for (int j = 0; j < 8; j++) {
                    int c = i * 8 + j;
                    float h = tanhf(__uint_as_float(d[c]) + gv[c] + sb0[coff + c]);
                    __nv_bfloat16 hb = __float2bfloat16(h);
                    ph.b[j] = hb;
                    pl.b[j] = __float2bfloat16(h - __bfloat162float(hb));
                }
                uint32_t off = (r << 7) + ((coff + i * 8) << 1);
                uint32_t sw = off ^ ((off >> 3) & 0x70);
                __stcg((uint4*)(oh + sw), ph.v);
                __stcg((uint4*)(ol + sw), pl.v);
            }
        }
        grid_sync();

        // ===== layer 1: D = H0c @ W1t^T + H1p @ U1t^T =====
        if (tid == 0) {
            Seg s0 = { g_H0_hi + (size_t)cu * HPAR + rb16,
                       g_H0_lo + (size_t)cu * HPAR + rb16,
                       g_W1t_hi + nb16, g_W1t_lo + nb16 };
            Seg s1 = { g_H1_hi + (size_t)pv * HPAR + rb16,
                       g_H1_lo + (size_t)pv * HPAR + rb16,
                       g_U1t_hi + nb16, g_U1t_lo + nb16 };
            ctrl_run(sbase, tmem, s0, s1, 2, nf, nc);
        }
        mbar_wait(sbase + 32, epi_ph & 1);
        epi_ph++;
        TC_FENCE_AFTER();
        {
            uint32_t d[32];
            LDTM_X32(d, tmem + coff);
            TC_WAIT_LD();
            TC_FENCE_BEFORE();
            char* oh = g_H1_hi + (size_t)cu * HPAR + otile;
            char* ol = g_H1_lo + (size_t)cu * HPAR + otile;
#pragma unroll
            for (int i = 0; i < 4; i++) {
                union { __nv_bfloat16 b[8]; uint4 v; } ph, pl;
#pragma unroll
                for (int j = 0; j < 8; j++) {
                    int c = i * 8 + j;
                    float h = tanhf(__uint_as_float(d[c]) + sb1[coff + c]);
                    __nv_bfloat16 hb = __float2bfloat16(h);
                    ph.b[j] = hb;
                    pl.b[j] = __float2bfloat16(h - __bfloat162float(hb));
                }
                uint32_t off = (r << 7) + ((coff + i * 8) << 1);
                uint32_t sw = off ^ ((off >> 3) & 0x70);
                __stcg((uint4*)(oh + sw), ph.v);
                __stcg((uint4*)(ol + sw), pl.v);
            }
        }
        grid_sync();
    }

    if (wid == 0) {
        asm volatile("tcgen05.relinquish_alloc_permit.cta_group::1.sync.aligned;" ::: "memory");
        asm volatile("tcgen05.dealloc.cta_group::1.sync.aligned.b32 %0, %1;"
                     :: "r"(tmem), "r"(64u) : "memory");
    }

#else
    // ---------------- fp32 fallback (proven R7 path) ----------------
    float* AsS = (float*)smem_raw;
    float* BsS = AsS + 2 * BK * ASTRIDE;
    const int tx = tid & 15;
    const int ty = tid >> 4;
    const int rowBase = (bid >> 4) << 7;
    const int colBase = (bid & 15) << 6;

    grid_sync();  // k_zero already zeroed parity-0 fp32 state

    const float4 b0v = *(const float4*)(b0 + colBase + (tx << 2));
    const float4 b1v = *(const float4*)(b1 + colBase + (tx << 2));

#pragma unroll 1
    for (int t = 0; t < T_; t++) {
        const int pv = t & 1;
        const int cu = pv ^ 1;
        const float* H0p = g_H0f + (size_t)pv * (B_ * U_);
        float* H0c = g_H0f + (size_t)cu * (B_ * U_);
        const float* H1p = g_H1f + (size_t)pv * (B_ * U_);
        float* H1c = g_H1f + (size_t)cu * (B_ * U_);

        float acc[8][4];
#pragma unroll
        for (int i = 0; i < 8; i++) {
            int r = rowBase + (ty << 3) + i;
            int idx = __ldg(inputs + r * T_ + t);
            float4 p = ld4_ro(g_EW0 + (size_t)idx * U_ + colBase + (tx << 2));
            acc[i][0] = p.x + b0v.x;
            acc[i][1] = p.y + b0v.y;
            acc[i][2] = p.z + b0v.z;
            acc[i][3] = p.w + b0v.w;
        }
        gemm_tile<true>(H0p, U_, B_ - 1, U0, U_, U_, rowBase, colBase, AsS, BsS, acc, tid);
#pragma unroll
        for (int i = 0; i < 8; i++) {
            int r = rowBase + (ty << 3) + i;
            float4 o = make_float4(tanhf(acc[i][0]), tanhf(acc[i][1]),
                                   tanhf(acc[i][2]), tanhf(acc[i][3]));
            __stcg((float4*)(H0c + (size_t)r * U_ + colBase + (tx << 2)), o);
        }
        grid_sync();

#pragma unroll
        for (int i = 0; i < 8; i++) {
            acc[i][0] = b1v.x;
            acc[i][1] = b1v.y;
            acc[i][2] = b1v.z;
            acc[i][3] = b1v.w;
        }
        gemm_tile<true>(H0c, U_, B_ - 1, W1, U_, U_, rowBase, colBase, AsS, BsS, acc, tid);
        gemm_tile<true>(H1p, U_, B_ - 1, U1, U_, U_, rowBase, colBase, AsS, BsS, acc, tid);
#pragma unroll
        for (int i = 0; i < 8; i++) {
            int r = rowBase + (ty << 3) + i;
            float4 o = make_float4(tanhf(acc[i][0]), tanhf(acc[i][1]),
                                   tanhf(acc[i][2]), tanhf(acc[i][3]));
            __stcg((float4*)(H1c + (size_t)r * U_ + colBase + (tx << 2)), o);
        }
        grid_sync();
    }
#endif
}

// ---------------------------------------------------------------------------
// k_out: out[b] = sigmoid(H1_final[b,:] . Wout + bout). Final parity = 0.
// ---------------------------------------------------------------------------
__global__ void __launch_bounds__(128) k_out(const float* __restrict__ Wout,
                                             const float* __restrict__ bout,
                                             float* __restrict__ out) {
    const int b = blockIdx.x;
    const int tid = threadIdx.x;
    float s = 0.f;
#if HAS_TC
    const int rbq = b >> 7;
    const int r = b & 127;
    const int u0 = tid << 3;
    const int cb = u0 >> 6;
    const int cl = u0 & 63;
    const char* th = g_H1_hi + ((size_t)rbq * 16 + cb) * HTILE;
    const char* tl = g_H1_lo + ((size_t)rbq * 16 + cb) * HTILE;
    uint32_t off = (r << 7) + (cl << 1);
    uint32_t sw = off ^ ((off >> 3) & 0x70);
    union { uint4 v; __nv_bfloat16 e[8]; } hv, lv;
    hv.v = *(const uint4*)(th + sw);
    lv.v = *(const uint4*)(tl + sw);
#pragma unroll
    for (int j = 0; j < 8; j++) {
        float h = __bfloat162float(hv.e[j]) + __bfloat162float(lv.e[j]);
        s += h * __ldg(Wout + u0 + j);
    }
#else
    const float* h = g_H1f + (size_t)b * U_;
    for (int u = tid; u < U_; u += 128) s += h[u] * Wout[u];
#endif
    __shared__ float red[128];
    red[tid] = s;
    __syncthreads();
    for (int o = 64; o > 0; o >>= 1) {
        if (tid < o) red[tid] += red[tid + o];
        __syncthreads();
    }
    if (tid == 0) {
        float z = red[0] + bout[0];
        out[b] = 1.f / (1.f + expf(-z));
    }
}

// ---------------------------------------------------------------------------
extern "C" void kernel_launch(void* const* d_in, const int* in_sizes, int n_in,
                              void* d_out, int out_size) {
    const int* inputs = (const int*)d_in[0];
    const float* emb = (const float*)d_in[1];
    const float* W0 = (const float*)d_in[2];
    const float* U0 = (const float*)d_in[3];
    const float* b0 = (const float*)d_in[4];
    const float* W1 = (const float*)d_in[5];
    const float* U1 = (const float*)d_in[6];
    const float* b1 = (const float*)d_in[7];
    const float* Wout = (const float*)d_in[8];
    const float* bout = (const float*)d_in[9];
    float* out = (float*)d_out;

    static bool attr_set = false;
    if (!attr_set) {
        cudaFuncSetAttribute(k_rnn, cudaFuncAttributeMaxDynamicSharedMemorySize, DSMEM);
        attr_set = true;
    }

    dim3 g1((V_ + BM - 1) / BM, U_ / BN);
    k_ew0<<<g1, 256>>>(emb, W0);
    k_prep<<<dim3(256, 3), 256>>>(U0, W1, U1);
    k_zero<<<(B_ * U_ / 4 + 255) / 256, 256>>>();
    k_rnn<<<NBLK, 256, DSMEM>>>(inputs, U0, b0, W1, U1, b1);
    k_out<<<B_, 128>>>(Wout, bout, out);
}

// round 12
// speedup vs baseline: 4.0363x; 1.0667x over previous
#include <cuda_runtime.h>
#include <cuda_bf16.h>
#include <cstdint>

// ---------------------------------------------------------------------------
// Feature gate: tcgen05 only exists in arch-accelerated device passes.
// Non-accelerated passes (compute_103 -> sm_103) compile the fp32 fallback.
// ---------------------------------------------------------------------------
#if defined(__CUDA_ARCH_FEAT_SM103_ALL) || defined(__CUDA_ARCH_FEAT_SM100_ALL) || \
    defined(__CUDA_ARCH_FEAT_SM101_ALL) || defined(__CUDA_ARCH_FEAT_SM110_ALL)
#define HAS_TC 1
#else
#define HAS_TC 0
#endif

// Problem constants
#define B_ 1024
#define T_ 256
#define V_ 50000
#define E_ 512
#define U_ 1024

// fp32 SGEMM tiling (k_ew0 + fallback)
#define BM 128
#define BN 64
#define BK 16
#define ASTRIDE (BM + 4)
#define NBLK 128

// tcgen05 recurrence
#define TM 128
#define TN 64
#define HTILE 16384                 // 128 rows x 128B (64 bf16), SW128-swizzled
#define WTILE 8192                  // 64 rows x 128B
#define HPAR  (128 * HTILE)         // one parity: 8 rb x 16 chunks
#define HBYTES (2 * HPAR)
#define WBYTES (256 * WTILE)

// SMEM header offsets (within 1KB header at aligned sbase)
#define MB_FULL0 0
#define MB_FULL1 8
#define MB_DONE0 16
#define MB_DONE1 24
#define MB_EPI0  32
#define MB_EPI1  40
#define TMEM_PTR 64
#define SLOT0 1024
// Slot layout: A (H tiles, 32KB) + B0 (U0/unused, 16KB) + B1 (W1/U1, 16KB)
#define A_HI 0
#define A_LO 16384
#define B0_HI 32768
#define B0_LO 40960
#define B1_HI 49152
#define B1_LO 57344
#define SLOTSZ 65536
#define DSMEM (1024 + SLOT0 + 2 * SLOTSZ)   // align pad + header + 2 slots

#define IDESC ((1u << 4) | (1u << 7) | (1u << 10) | ((TN / 8) << 17) | ((TM / 16) << 24))

// Device scratch (allocation-free per harness rules)
__device__ float g_EW0[(size_t)V_ * U_];
// fp32 fallback state
__device__ float g_H0f[2 * B_ * U_];
__device__ float g_H1f[2 * B_ * U_];
// tile-format split-bf16 state
__device__ __align__(1024) char g_H0_hi[HBYTES];
__device__ __align__(1024) char g_H0_lo[HBYTES];
__device__ __align__(1024) char g_H1_hi[HBYTES];
__device__ __align__(1024) char g_H1_lo[HBYTES];
__device__ __align__(1024) char g_U0t_hi[WBYTES];
__device__ __align__(1024) char g_U0t_lo[WBYTES];
__device__ __align__(1024) char g_W1t_hi[WBYTES];
__device__ __align__(1024) char g_W1t_lo[WBYTES];
__device__ __align__(1024) char g_U1t_hi[WBYTES];
__device__ __align__(1024) char g_U1t_lo[WBYTES];
// global barrier (fallback)
__device__ unsigned g_bar_count = 0;
__device__ volatile unsigned g_bar_gen = 0;
// row-block group barriers (TC path): 8 groups, padded to 128B
__device__ unsigned g_gc[8 * 32];
__device__ volatile unsigned g_gg[8 * 32];

// ---------------------------------------------------------------------------
// Common helpers
// ---------------------------------------------------------------------------
__device__ __forceinline__ float4 ld4_ro(const float* p) { return __ldg((const float4*)p); }
__device__ __forceinline__ float4 ld4_cg(const float* p) { return __ldcg((const float4*)p); }

__device__ __forceinline__ void grid_sync() {
    __syncthreads();
    if (threadIdx.x == 0) {
        __threadfence();
        unsigned g = g_bar_gen;
        unsigned a = atomicAdd(&g_bar_count, 1);
        if (a == NBLK - 1) {
            g_bar_count = 0;
            __threadfence();
            g_bar_gen = g + 1;
        } else {
            while (g_bar_gen == g) { __nanosleep(32); }
        }
        __threadfence();
    }
    __syncthreads();
}

#if HAS_TC
// ---------------------------------------------------------------------------
// tcgen05 / bulk-copy / mbarrier PTX helpers (accelerated pass only)
// ---------------------------------------------------------------------------
__device__ __forceinline__ uint32_t smem_u32(const void* p) {
    return (uint32_t)__cvta_generic_to_shared(p);
}
__device__ __forceinline__ void mbar_init(uint32_t a, uint32_t cnt) {
    asm volatile("mbarrier.init.shared.b64 [%0], %1;" :: "r"(a), "r"(cnt) : "memory");
}
__device__ __forceinline__ void mbar_expect(uint32_t a, uint32_t bytes) {
    asm volatile("mbarrier.arrive.expect_tx.shared.b64 _, [%0], %1;"
                 :: "r"(a), "r"(bytes) : "memory");
}
__device__ __forceinline__ void mbar_wait(uint32_t a, uint32_t parity) {
    asm volatile(
        "{\n\t.reg .pred P;\n\t"
        "WL%=:\n\t"
        "mbarrier.try_wait.parity.acquire.cta.shared::cta.b64 P, [%0], %1, 0x989680;\n\t"
        "@P bra WD%=;\n\t"
        "bra WL%=;\n\t"
        "WD%=:\n\t}"
        :: "r"(a), "r"(parity) : "memory");
}
__device__ __forceinline__ void bulk_g2s(uint32_t dst, const void* src,
                                         uint32_t bytes, uint32_t mbar) {
    asm volatile(
        "cp.async.bulk.shared::cta.global.mbarrier::complete_tx::bytes [%0], [%1], %2, [%3];"
        :: "r"(dst), "l"(src), "r"(bytes), "r"(mbar) : "memory");
}
__device__ __forceinline__ uint64_t sdesc(uint32_t addr) {
    // SW128 K-major: layout=2, version=1, SBO=64, LBO=1
    return 0x4000404000010000ULL | ((uint64_t)(addr >> 4) & 0x3FFF);
}
__device__ __forceinline__ void mma_f16_ss(uint32_t d, uint64_t ad, uint64_t bd,
                                           uint32_t idesc, uint32_t en) {
    asm volatile(
        "{\n\t.reg .pred p;\n\t"
        "setp.ne.u32 p, %4, 0;\n\t"
        "tcgen05.mma.cta_group::1.kind::f16 [%0], %1, %2, %3, {%5, %5, %5, %5}, p;\n\t}"
        :: "r"(d), "l"(ad), "l"(bd), "r"(idesc), "r"(en), "r"(0u) : "memory");
}
__device__ __forceinline__ void mma_commit(uint32_t mbar) {
    asm volatile(
        "tcgen05.commit.cta_group::1.mbarrier::arrive::one.shared::cluster.b64 [%0];"
        :: "r"(mbar) : "memory");
}
// 3-pass split-bf16 product: Ahi*Bhi + Alo*Bhi + Ahi*Blo (K=64 via 4x K16)
__device__ __forceinline__ void mma_triple(uint32_t dbuf, uint64_t dAh, uint64_t dAl,
                                           uint64_t dBh, uint64_t dBl, uint32_t en_first) {
    uint32_t en = en_first;
#pragma unroll
    for (int k = 0; k < 4; k++) { mma_f16_ss(dbuf, dAh + k * 2, dBh + k * 2, IDESC, en); en = 1u; }
#pragma unroll
    for (int k = 0; k < 4; k++) mma_f16_ss(dbuf, dAl + k * 2, dBh + k * 2, IDESC, 1u);
#pragma unroll
    for (int k = 0; k < 4; k++) mma_f16_ss(dbuf, dAh + k * 2, dBl + k * 2, IDESC, 1u);
}
#define TC_FENCE_AFTER()  asm volatile("tcgen05.fence::after_thread_sync;" ::: "memory")
#define TC_FENCE_BEFORE() asm volatile("tcgen05.fence::before_thread_sync;" ::: "memory")
#define TC_WAIT_LD()      asm volatile("tcgen05.wait::ld.sync.aligned;" ::: "memory")

#define LDTM_X32(r, ta) \
    asm volatile( \
        "tcgen05.ld.sync.aligned.32x32b.x32.b32 " \
        "{%0, %1, %2, %3, %4, %5, %6, %7, " \
        " %8, %9, %10, %11, %12, %13, %14, %15, " \
        " %16, %17, %18, %19, %20, %21, %22, %23, " \
        " %24, %25, %26, %27, %28, %29, %30, %31}, [%32];" \
        : "=r"((r)[0]),  "=r"((r)[1]),  "=r"((r)[2]),  "=r"((r)[3]), \
          "=r"((r)[4]),  "=r"((r)[5]),  "=r"((r)[6]),  "=r"((r)[7]), \
          "=r"((r)[8]),  "=r"((r)[9]),  "=r"((r)[10]), "=r"((r)[11]), \
          "=r"((r)[12]), "=r"((r)[13]), "=r"((r)[14]), "=r"((r)[15]), \
          "=r"((r)[16]), "=r"((r)[17]), "=r"((r)[18]), "=r"((r)[19]), \
          "=r"((r)[20]), "=r"((r)[21]), "=r"((r)[22]), "=r"((r)[23]), \
          "=r"((r)[24]), "=r"((r)[25]), "=r"((r)[26]), "=r"((r)[27]), \
          "=r"((r)[28]), "=r"((r)[29]), "=r"((r)[30]), "=r"((r)[31]) \
        : "r"(ta))

// Row-block group barrier: 16 CTAs sharing rb. All state deps are rb-local.
__device__ __forceinline__ void rb_sync(int rb) {
    __syncthreads();
    asm volatile("fence.proxy.async;" ::: "memory");
    if (threadIdx.x == 0) {
        __threadfence();
        unsigned g = g_gg[rb * 32];
        unsigned a = atomicAdd(&g_gc[rb * 32], 1);
        if (a == 15) {
            g_gc[rb * 32] = 0;
            __threadfence();
            g_gg[rb * 32] = g + 1;
        } else {
            while (g_gg[rb * 32] == g) { __nanosleep(32); }
        }
        __threadfence();
    }
    __syncthreads();
}
#endif  // HAS_TC

// ---------------------------------------------------------------------------
// fp32 SGEMM building blocks (k_ew0 always; k_rnn fallback)
// ---------------------------------------------------------------------------
template <bool ACG>
__device__ __forceinline__ void gt_loadA(float4 aR[2], const float* A, int lda,
                                         int rowBase, int kBase, int maxRow, int tid) {
#pragma unroll
    for (int j = 0; j < 2; j++) {
        int i = tid + (j << 8);
        int arow = i >> 2;
        int acol = (i & 3) << 2;
        int r = rowBase + arow;
        if (r > maxRow) r = maxRow;
        const float* p = A + (size_t)r * lda + kBase + acol;
        aR[j] = ACG ? ld4_cg(p) : ld4_ro(p);
    }
}
__device__ __forceinline__ void gt_storeA(const float4 aR[2], float* AsBuf, int tid) {
#pragma unroll
    for (int j = 0; j < 2; j++) {
        int i = tid + (j << 8);
        int arow = i >> 2;
        int acol = (i & 3) << 2;
        AsBuf[(acol + 0) * ASTRIDE + arow] = aR[j].x;
        AsBuf[(acol + 1) * ASTRIDE + arow] = aR[j].y;
        AsBuf[(acol + 2) * ASTRIDE + arow] = aR[j].z;
        AsBuf[(acol + 3) * ASTRIDE + arow] = aR[j].w;
    }
}
__device__ __forceinline__ void gt_loadB(float4& bR, const float* Bm, int ldb,
                                         int colBase, int kBase, int tid) {
    int brow = tid >> 4;
    int bcol = (tid & 15) << 2;
    bR = ld4_ro(Bm + (size_t)(kBase + brow) * ldb + colBase + bcol);
}
__device__ __forceinline__ void gt_storeB(const float4 bR, float* BsBuf, int tid) {
    int brow = tid >> 4;
    int bcol = (tid & 15) << 2;
    *(float4*)(BsBuf + brow * BN + bcol) = bR;
}

template <bool ACG>
__device__ __forceinline__ void gemm_tile(const float* __restrict__ A, int lda, int maxRow,
                                          const float* __restrict__ Bm, int ldb, int K,
                                          int rowBase, int colBase,
                                          float* AsS, float* BsS,
                                          float acc[8][4], int tid) {
    const int ABUF = BK * ASTRIDE;
    const int BBUF = BK * BN;
    const int tx = tid & 15;
    const int ty = tid >> 4;
    float4 aR[2];
    float4 bR;
    gt_loadA<ACG>(aR, A, lda, rowBase, 0, maxRow, tid);
    gt_loadB(bR, Bm, ldb, colBase, 0, tid);
    gt_storeA(aR, AsS, tid);
    gt_storeB(bR, BsS, tid);
    __syncthreads();
    const int nC = K >> 4;
#pragma unroll 2
    for (int c = 0; c < nC; c++) {
        const int cur = c & 1;
        if (c + 1 < nC) {
            gt_loadA<ACG>(aR, A, lda, rowBase, (c + 1) << 4, maxRow, tid);
            gt_loadB(bR, Bm, ldb, colBase, (c + 1) << 4, tid);
        }
        const float* As = AsS + cur * ABUF;
        const float* Bs = BsS + cur * BBUF;
#pragma unroll 8
        for (int k = 0; k < BK; k++) {
            float4 a0 = *(const float4*)(As + k * ASTRIDE + (ty << 3));
            float4 a1 = *(const float4*)(As + k * ASTRIDE + (ty << 3) + 4);
            float4 bv = *(const float4*)(Bs + k * BN + (tx << 2));
            float av[8] = {a0.x, a0.y, a0.z, a0.w, a1.x, a1.y, a1.z, a1.w};
            float bw[4] = {bv.x, bv.y, bv.z, bv.w};
#pragma unroll
            for (int i = 0; i < 8; i++)
#pragma unroll
                for (int j = 0; j < 4; j++)
                    acc[i][j] = fmaf(av[i], bw[j], acc[i][j]);
        }
        if (c + 1 < nC) {
            gt_storeA(aR, AsS + (cur ^ 1) * ABUF, tid);
            gt_storeB(bR, BsS + (cur ^ 1) * BBUF, tid);
        }
        __syncthreads();
    }
}

// ---------------------------------------------------------------------------
// k_ew0: EW0[V,U] = emb[V,E] @ W0[E,U]  (fp32, both paths)
// ---------------------------------------------------------------------------
__global__ void __launch_bounds__(256) k_ew0(const float* __restrict__ emb,
                                             const float* __restrict__ W0) {
    __shared__ float AsS[2 * BK * ASTRIDE];
    __shared__ float BsS[2 * BK * BN];
    const int tid = threadIdx.x;
    const int tx = tid & 15;
    const int ty = tid >> 4;
    const int rowBase = blockIdx.x << 7;
    const int colBase = blockIdx.y << 6;
    float acc[8][4];
#pragma unroll
    for (int i = 0; i < 8; i++)
#pragma unroll
        for (int j = 0; j < 4; j++) acc[i][j] = 0.f;
    gemm_tile<false>(emb, E_, V_ - 1, W0, U_, E_, rowBase, colBase, AsS, BsS, acc, tid);
#pragma unroll
    for (int i = 0; i < 8; i++) {
        int r = rowBase + (ty << 3) + i;
        if (r < V_) {
            float4 o = make_float4(acc[i][0], acc[i][1], acc[i][2], acc[i][3]);
            *(float4*)(g_EW0 + (size_t)r * U_ + colBase + (tx << 2)) = o;
        }
    }
}

// ---------------------------------------------------------------------------
// k_prep: transposed split-bf16 weight tiles (SW128, K-major). Cheap; both paths.
// ---------------------------------------------------------------------------
__global__ void __launch_bounds__(256) k_prep(const float* __restrict__ U0,
                                              const float* __restrict__ W1,
                                              const float* __restrict__ U1) {
    const float* W = (blockIdx.y == 0) ? U0 : (blockIdx.y == 1 ? W1 : U1);
    char* dh = (blockIdx.y == 0) ? g_U0t_hi : (blockIdx.y == 1 ? g_W1t_hi : g_U1t_hi);
    char* dl = (blockIdx.y == 0) ? g_U0t_lo : (blockIdx.y == 1 ? g_W1t_lo : g_U1t_lo);
    const int nb = blockIdx.x >> 4;
    const int c = blockIdx.x & 15;
    char* th = dh + (size_t)blockIdx.x * WTILE;
    char* tl = dl + (size_t)blockIdx.x * WTILE;
    const int tid = threadIdx.x;
    for (int i = tid; i < 512; i += 256) {
        int nl = i >> 3;
        int kg = i & 7;
        int n = (nb << 6) + nl;
        int kbase = (c << 6) + (kg << 3);
        union { __nv_bfloat16 b[8]; uint4 v; } ph, pl;
#pragma unroll
        for (int j = 0; j < 8; j++) {
            float v = __ldg(W + (size_t)(kbase + j) * U_ + n);
            __nv_bfloat16 hb = __float2bfloat16(v);
            ph.b[j] = hb;
            pl.b[j] = __float2bfloat16(v - __bfloat162float(hb));
        }
        uint32_t off = (nl << 7) + (kg << 4);
        uint32_t sw = off ^ ((off >> 3) & 0x70);
        *(uint4*)(th + sw) = ph.v;
        *(uint4*)(tl + sw) = pl.v;
    }
}

// Zero parity-0 state (both representations; must re-zero every launch)
__global__ void __launch_bounds__(256) k_zero() {
    size_t i = (size_t)blockIdx.x * blockDim.x + threadIdx.x;  // 16B units
    uint4 z = make_uint4(0, 0, 0, 0);
    if (i < (size_t)B_ * U_ / 4) {
        ((uint4*)g_H0f)[i] = z;
        ((uint4*)g_H1f)[i] = z;
    }
    if (i < HPAR / 16) {
        ((uint4*)g_H0_hi)[i] = z;
        ((uint4*)g_H0_lo)[i] = z;
        ((uint4*)g_H1_hi)[i] = z;
        ((uint4*)g_H1_lo)[i] = z;
    }
}

// ---------------------------------------------------------------------------
// k_rnn: persistent recurrence. 128 CTAs x 256 threads.
//   HAS_TC : merged-phase split-bf16 tcgen05 pipeline.
//     Phase p (p = 0..T): concurrently compute
//       L0(t=p):   buf0 = H0[par p&1] @ U0      (if p < T)
//       L1(t=p-1): buf1 = H0[par p&1] @ W1 + H1[par (p-1)&1] @ U1   (if p >= 1)
//     The H0 A-tiles are SHARED between the U0 and W1 passes (one copy, two MMAs).
//     One rb-local barrier per phase publishes H0c(p) and H1c(p-1).
//   else   : proven fp32 FFMA SGEMM path
// ---------------------------------------------------------------------------
__global__ void __launch_bounds__(256, 1) k_rnn(
    const int* __restrict__ inputs,
    const float* __restrict__ U0, const float* __restrict__ b0,
    const float* __restrict__ W1, const float* __restrict__ U1,
    const float* __restrict__ b1) {
    extern __shared__ __align__(16) char smem_raw[];
    const int tid = threadIdx.x;
    const int bid = blockIdx.x;

#if HAS_TC
    // ---------------- tcgen05 merged-phase path ----------------
    const int wid = tid >> 5;
    const int lane = tid & 31;
    const int rb = bid >> 4;
    const int nb = bid & 15;
    const int rowBase = rb << 7;
    const int colBase = nb << 6;
    const int r = ((wid & 3) << 5) + lane;   // M row in tile (0..127)
    const int coff = (wid >> 2) << 5;        // column half: 0 or 32
    const size_t rb16 = (size_t)rb * 16 * HTILE;
    const size_t nb16 = (size_t)nb * 16 * WTILE;
    const size_t otile = ((size_t)rb * 16 + nb) * HTILE;

    uint32_t raw = smem_u32(smem_raw);
    uint32_t sbase = (raw + 1023) & ~1023u;
    char* sgen = smem_raw + (sbase - raw);
    float* sb0 = (float*)(sgen + 128);
    float* sb1 = (float*)(sgen + 384);

    if (tid == 0) {
        mbar_init(sbase + MB_FULL0, 1);
        mbar_init(sbase + MB_FULL1, 1);
        mbar_init(sbase + MB_DONE0, 1);
        mbar_init(sbase + MB_DONE1, 1);
        mbar_init(sbase + MB_EPI0, 1);
        mbar_init(sbase + MB_EPI1, 1);
    }
    if (tid < 64) {
        sb0[tid] = b0[colBase + tid];
        sb1[tid] = b1[colBase + tid];
    }
    if (wid == 0) {
        asm volatile("tcgen05.alloc.cta_group::1.sync.aligned.shared::cta.b32 [%0], %1;"
                     :: "r"(sbase + TMEM_PTR), "r"(128u) : "memory");
    }
    __syncthreads();
    uint32_t tmem;
    asm volatile("ld.shared.b32 %0, [%1];" : "=r"(tmem) : "r"(sbase + TMEM_PTR));
    const uint32_t buf0 = tmem;
    const uint32_t buf1 = tmem + 64;

    int nf[2] = {0, 0}, nc[2] = {0, 0};
    int epi0_ph = 0, epi1_ph = 0;

#pragma unroll 1
    for (int p = 0; p <= T_; p++) {
        const bool do0 = (p < T_);
        const bool do1 = (p >= 1);
        const int pv = p & 1;

        // ---- control: stream copies + issue MMAs (tid 0) ----
        if (tid == 0) {
            const char* Ah = g_H0_hi + (size_t)pv * HPAR + rb16;
            const char* Al = g_H0_lo + (size_t)pv * HPAR + rb16;
            const char* B0h = g_U0t_hi + nb16;
            const char* B0l = g_U0t_lo + nb16;
            const char* B1h = g_W1t_hi + nb16;
            const char* B1l = g_W1t_lo + nb16;
            const char* A2h = g_H1_hi + (size_t)((p - 1) & 1) * HPAR + rb16;
            const char* A2l = g_H1_lo + (size_t)((p - 1) & 1) * HPAR + rb16;
            const char* B2h = g_U1t_hi + nb16;
            const char* B2l = g_U1t_lo + nb16;

            const int nT = do1 ? 32 : 16;
            const uint32_t abytes = 32768u + (do0 ? 16384u : 0u) + (do1 ? 16384u : 0u);

            auto fill = [&](int gc) {
                int s = gc & 1;
                if (nf[s] > 0) mbar_wait(sbase + MB_DONE0 + s * 8, (nf[s] - 1) & 1);
                uint32_t fb = sbase + MB_FULL0 + s * 8;
                uint32_t dst = sbase + SLOT0 + s * SLOTSZ;
                if (gc < 16) {
                    mbar_expect(fb, abytes);
                    bulk_g2s(dst + A_HI, Ah + (size_t)gc * HTILE, HTILE, fb);
                    bulk_g2s(dst + A_LO, Al + (size_t)gc * HTILE, HTILE, fb);
                    if (do0) {
                        bulk_g2s(dst + B0_HI, B0h + (size_t)gc * WTILE, WTILE, fb);
                        bulk_g2s(dst + B0_LO, B0l + (size_t)gc * WTILE, WTILE, fb);
                    }
                    if (do1) {
                        bulk_g2s(dst + B1_HI, B1h + (size_t)gc * WTILE, WTILE, fb);
                        bulk_g2s(dst + B1_LO, B1l + (size_t)gc * WTILE, WTILE, fb);
                    }
                } else {
                    int c = gc - 16;
                    mbar_expect(fb, 49152u);
                    bulk_g2s(dst + A_HI, A2h + (size_t)c * HTILE, HTILE, fb);
                    bulk_g2s(dst + A_LO, A2l + (size_t)c * HTILE, HTILE, fb);
                    bulk_g2s(dst + B1_HI, B2h + (size_t)c * WTILE, WTILE, fb);
                    bulk_g2s(dst + B1_LO, B2l + (size_t)c * WTILE, WTILE, fb);
                }
                nf[s]++;
            };

            fill(0);
            fill(1);
            for (int gc = 0; gc < nT; gc++) {
                int s = gc & 1;
                mbar_wait(sbase + MB_FULL0 + s * 8, nc[s] & 1);
                uint32_t sa = sbase + SLOT0 + s * SLOTSZ;
                uint64_t dAh = sdesc(sa + A_HI), dAl = sdesc(sa + A_LO);
                if (gc < 16) {
                    if (do0)
                        mma_triple(buf0, dAh, dAl, sdesc(sa + B0_HI), sdesc(sa + B0_LO),
                                   (gc > 0) ? 1u : 0u);
                    if (do1)
                        mma_triple(buf1, dAh, dAl, sdesc(sa + B1_HI), sdesc(sa + B1_LO),
                                   (gc > 0) ? 1u : 0u);
                } else {
                    mma_triple(buf1, dAh, dAl, sdesc(sa + B1_HI), sdesc(sa + B1_LO), 1u);
                }
                mma_commit(sbase + MB_DONE0 + s * 8);
                nc[s]++;
                if (gc == 15 && do0) mma_commit(sbase + MB_EPI0);
                if (gc == nT - 1 && do1) mma_commit(sbase + MB_EPI1);
                if (gc + 2 < nT) fill(gc + 2);
            }
        }

        // ---- epilogue 0: H0c(p) = tanh(buf0 + EW0[idx] + b0) ----
        if (do0) {
            const int idx = __ldg(inputs + (rowBase + r) * T_ + p);
            float gv[32];
#pragma unroll
            for (int i = 0; i < 8; i++) {
                float4 g4 = ld4_ro(g_EW0 + (size_t)idx * U_ + colBase + coff + i * 4);
                gv[i * 4 + 0] = g4.x; gv[i * 4 + 1] = g4.y;
                gv[i * 4 + 2] = g4.z; gv[i * 4 + 3] = g4.w;
            }
            mbar_wait(sbase + MB_EPI0, epi0_ph & 1);
            epi0_ph++;
            TC_FENCE_AFTER();
            uint32_t d[32];
            LDTM_X32(d, buf0 + coff);
            TC_WAIT_LD();
            TC_FENCE_BEFORE();
            char* oh = g_H0_hi + (size_t)((p + 1) & 1) * HPAR + otile;
            char* ol = g_H0_lo + (size_t)((p + 1) & 1) * HPAR + otile;
#pragma unroll
            for (int i = 0; i < 4; i++) {
                union { __nv_bfloat16 b[8]; uint4 v; } ph, pl;
#pragma unroll
                for (int j = 0; j < 8; j++) {
                    int c = i * 8 + j;
                    float h = tanhf(__uint_as_float(d[c]) + gv[c] + sb0[coff + c]);
                    __nv_bfloat16 hb = __float2bfloat16(h);
                    ph.b[j] = hb;
                    pl.b[j] = __float2bfloat16(h - __bfloat162float(hb));
                }
                uint32_t off = (r << 7) + ((coff + i * 8) << 1);
                uint32_t sw = off ^ ((off >> 3) & 0x70);
                __stcg((uint4*)(oh + sw), ph.v);
                __stcg((uint4*)(ol + sw), pl.v);
            }
        }

        // ---- epilogue 1: H1c(p-1) = tanh(buf1 + b1) ----
        if (do1) {
            mbar_wait(sbase + MB_EPI1, epi1_ph & 1);
            epi1_ph++;
            TC_FENCE_AFTER();
            uint32_t d[32];
            LDTM_X32(d, buf1 + coff);
            TC_WAIT_LD();
            TC_FENCE_BEFORE();
            char* oh = g_H1_hi + (size_t)(p & 1) * HPAR + otile;
            char* ol = g_H1_lo + (size_t)(p & 1) * HPAR + otile;
#pragma unroll
            for (int i = 0; i < 4; i++) {
                union { __nv_bfloat16 b[8]; uint4 v; } ph, pl;
#pragma unroll
                for (int j = 0; j < 8; j++) {
                    int c = i * 8 + j;
                    float h = tanhf(__uint_as_float(d[c]) + sb1[coff + c]);
                    __nv_bfloat16 hb = __float2bfloat16(h);
                    ph.b[j] = hb;
                    pl.b[j] = __float2bfloat16(h - __bfloat162float(hb));
                }
                uint32_t off = (r << 7) + ((coff + i * 8) << 1);
                uint32_t sw = off ^ ((off >> 3) & 0x70);
                __stcg((uint4*)(oh + sw), ph.v);
                __stcg((uint4*)(ol + sw), pl.v);
            }
        }

        rb_sync(rb);
    }

    if (wid == 0) {
        asm volatile("tcgen05.relinquish_alloc_permit.cta_group::1.sync.aligned;" ::: "memory");
        asm volatile("tcgen05.dealloc.cta_group::1.sync.aligned.b32 %0, %1;"
                     :: "r"(tmem), "r"(128u) : "memory");
    }

#else
    // ---------------- fp32 fallback (proven R7 path) ----------------
    float* AsS = (float*)smem_raw;
    float* BsS = AsS + 2 * BK * ASTRIDE;
    const int tx = tid & 15;
    const int ty = tid >> 4;
    const int rowBase = (bid >> 4) << 7;
    const int colBase = (bid & 15) << 6;

    grid_sync();

    const float4 b0v = *(const float4*)(b0 + colBase + (tx << 2));
    const float4 b1v = *(const float4*)(b1 + colBase + (tx << 2));

#pragma unroll 1
    for (int t = 0; t < T_; t++) {
        const int pv = t & 1;
        const int cu = pv ^ 1;
        const float* H0p = g_H0f + (size_t)pv * (B_ * U_);
        float* H0c = g_H0f + (size_t)cu * (B_ * U_);
        const float* H1p = g_H1f + (size_t)pv * (B_ * U_);
        float* H1c = g_H1f + (size_t)cu * (B_ * U_);

        float acc[8][4];
#pragma unroll
        for (int i = 0; i < 8; i++) {
            int r = rowBase + (ty << 3) + i;
            int idx = __ldg(inputs + r * T_ + t);
            float4 p = ld4_ro(g_EW0 + (size_t)idx * U_ + colBase + (tx << 2));
            acc[i][0] = p.x + b0v.x;
            acc[i][1] = p.y + b0v.y;
            acc[i][2] = p.z + b0v.z;
            acc[i][3] = p.w + b0v.w;
        }
        gemm_tile<true>(H0p, U_, B_ - 1, U0, U_, U_, rowBase, colBase, AsS, BsS, acc, tid);
#pragma unroll
        for (int i = 0; i < 8; i++) {
            int r = rowBase + (ty << 3) + i;
            float4 o = make_float4(tanhf(acc[i][0]), tanhf(acc[i][1]),
                                   tanhf(acc[i][2]), tanhf(acc[i][3]));
            __stcg((float4*)(H0c + (size_t)r * U_ + colBase + (tx << 2)), o);
        }
        grid_sync();

#pragma unroll
        for (int i = 0; i < 8; i++) {
            acc[i][0] = b1v.x;
            acc[i][1] = b1v.y;
            acc[i][2] = b1v.z;
            acc[i][3] = b1v.w;
        }
        gemm_tile<true>(H0c, U_, B_ - 1, W1, U_, U_, rowBase, colBase, AsS, BsS, acc, tid);
        gemm_tile<true>(H1p, U_, B_ - 1, U1, U_, U_, rowBase, colBase, AsS, BsS, acc, tid);
#pragma unroll
        for (int i = 0; i < 8; i++) {
            int r = rowBase + (ty << 3) + i;
            float4 o = make_float4(tanhf(acc[i][0]), tanhf(acc[i][1]),
                                   tanhf(acc[i][2]), tanhf(acc[i][3]));
            __stcg((float4*)(H1c + (size_t)r * U_ + colBase + (tx << 2)), o);
        }
        grid_sync();
    }
#endif
}

// ---------------------------------------------------------------------------
// k_out: out[b] = sigmoid(H1_final[b,:] . Wout + bout). Final parity = 0.
// ---------------------------------------------------------------------------
__global__ void __launch_bounds__(128) k_out(const float* __restrict__ Wout,
                                             const float* __restrict__ bout,
                                             float* __restrict__ out) {
    const int b = blockIdx.x;
    const int tid = threadIdx.x;
    float s = 0.f;
#if HAS_TC
    const int rbq = b >> 7;
    const int r = b & 127;
    const int u0 = tid << 3;
    const int cb = u0 >> 6;
    const int cl = u0 & 63;
    const char* th = g_H1_hi + ((size_t)rbq * 16 + cb) * HTILE;
    const char* tl = g_H1_lo + ((size_t)rbq * 16 + cb) * HTILE;
    uint32_t off = (r << 7) + (cl << 1);
    uint32_t sw = off ^ ((off >> 3) & 0x70);
    union { uint4 v; __nv_bfloat16 e[8]; } hv, lv;
    hv.v = *(const uint4*)(th + sw);
    lv.v = *(const uint4*)(tl + sw);
#pragma unroll
    for (int j = 0; j < 8; j++) {
        float h = __bfloat162float(hv.e[j]) + __bfloat162float(lv.e[j]);
        s += h * __ldg(Wout + u0 + j);
    }
#else
    const float* h = g_H1f + (size_t)b * U_;
    for (int u = tid; u < U_; u += 128) s += h[u] * Wout[u];
#endif
    __shared__ float red[128];
    red[tid] = s;
    __syncthreads();
    for (int o = 64; o > 0; o >>= 1) {
        if (tid < o) red[tid] += red[tid + o];
        __syncthreads();
    }
    if (tid == 0) {
        float z = red[0] + bout[0];
        out[b] = 1.f / (1.f + expf(-z));
    }
}

// ---------------------------------------------------------------------------
extern "C" void kernel_launch(void* const* d_in, const int* in_sizes, int n_in,
                              void* d_out, int out_size) {
    const int* inputs = (const int*)d_in[0];
    const float* emb = (const float*)d_in[1];
    const float* W0 = (const float*)d_in[2];
    const float* U0 = (const float*)d_in[3];
    const float* b0 = (const float*)d_in[4];
    const float* W1 = (const float*)d_in[5];
    const float* U1 = (const float*)d_in[6];
    const float* b1 = (const float*)d_in[7];
    const float* Wout = (const float*)d_in[8];
    const float* bout = (const float*)d_in[9];
    float* out = (float*)d_out;

    static bool attr_set = false;
    if (!attr_set) {
        cudaFuncSetAttribute(k_rnn, cudaFuncAttributeMaxDynamicSharedMemorySize, DSMEM);
        attr_set = true;
    }

    dim3 g1((V_ + BM - 1) / BM, U_ / BN);
    k_ew0<<<g1, 256>>>(emb, W0);
    k_prep<<<dim3(256, 3), 256>>>(U0, W1, U1);
    k_zero<<<(B_ * U_ / 4 + 255) / 256, 256>>>();
    k_rnn<<<NBLK, 256, DSMEM>>>(inputs, U0, b0, W1, U1, b1);
    k_out<<<B_, 128>>>(Wout, bout, out);
}